// round 13
// baseline (speedup 1.0000x reference)
#include <cuda_runtime.h>
#include <cuda_bf16.h>
#include <math.h>
#include <stdint.h>

#define B_ 16
#define T_ 2048
#define C_ 512
#define H_ 64
#define SW 36   /* smem plane row stride in 32-bit words (72 bf16, 144 B) */

// Global scratch: bf16 hi/lo planes (allowed __device__ scratch path)
__device__ __nv_bfloat16 g_qhi[B_*T_*H_], g_qlo[B_*T_*H_];
__device__ __nv_bfloat16 g_khi[B_*T_*H_], g_klo[B_*T_*H_];   // pre-scaled by 0.125
__device__ __nv_bfloat16 g_vthi[B_*H_*T_], g_vtlo[B_*H_*T_]; // [b][h][t]
__device__ __nv_bfloat16 g_erhi[T_*H_], g_erlo[T_*H_];

// 36 used 16x16 G segments for the 128-row tile: value = ta*8 + c16
__constant__ unsigned char G_SEGS[36] = {
    24,17,10,3,  32,25,18,11,  40,33,26,19,  48,41,34,27,
    56,49,42,35, 64,57,50,43,  72,65,58,51,  80,73,66,59,
    88,81,74,67
};

// ---------------------------------------------------------------------------
// helpers
// ---------------------------------------------------------------------------
__device__ __forceinline__ void bsplit(float x, __nv_bfloat16& h, __nv_bfloat16& l) {
    h = __float2bfloat16_rn(x);
    l = __float2bfloat16_rn(x - __bfloat162float(h));
}
__device__ __forceinline__ uint32_t smem_u32(const void* p) {
    return (uint32_t)__cvta_generic_to_shared(p);
}
__device__ __forceinline__ void ldsm_x4(uint32_t addr,
    uint32_t& r0, uint32_t& r1, uint32_t& r2, uint32_t& r3)
{
    asm volatile("ldmatrix.sync.aligned.m8n8.x4.shared.b16 {%0,%1,%2,%3}, [%4];"
        : "=r"(r0), "=r"(r1), "=r"(r2), "=r"(r3) : "r"(addr));
}
__device__ __forceinline__ void mmabf(float* c,
    uint32_t a0, uint32_t a1, uint32_t a2, uint32_t a3, uint32_t b0, uint32_t b1)
{
    asm volatile(
        "mma.sync.aligned.m16n8k16.row.col.f32.bf16.bf16.f32 "
        "{%0,%1,%2,%3}, {%4,%5,%6,%7}, {%8,%9}, {%0,%1,%2,%3};"
        : "+f"(c[0]), "+f"(c[1]), "+f"(c[2]), "+f"(c[3])
        : "r"(a0), "r"(a1), "r"(a2), "r"(a3), "r"(b0), "r"(b1));
}

// acc[2][4] += A(16 rows @ar0, 2-plane) x B^T(16 cols @n0*8, 2-plane)
__device__ __forceinline__ void gemm16(
    const uint32_t* __restrict__ Ah, const uint32_t* __restrict__ Al, int ar0,
    const uint32_t* __restrict__ Bh, const uint32_t* __restrict__ Bl, int n0,
    int lane, float (*acc)[4])
{
    const int la = lane & 7, l8 = (lane >> 3) & 1, l16 = lane >> 4;
    uint32_t aAh = smem_u32(Ah + (ar0 + la + l8*8)*SW) + l16*16;
    uint32_t aAl = smem_u32(Al + (ar0 + la + l8*8)*SW) + l16*16;
    uint32_t aBh = smem_u32(Bh + ((n0 + l16)*8 + la)*SW) + l8*16;
    uint32_t aBl = smem_u32(Bl + ((n0 + l16)*8 + la)*SW) + l8*16;
    #pragma unroll
    for (int ck = 0; ck < 4; ++ck) {
        uint32_t a0h,a1h,a2h,a3h, a0l,a1l,a2l,a3l;
        uint32_t p0h,p1h,q0h,q1h, p0l,p1l,q0l,q1l;
        ldsm_x4(aAh + ck*32, a0h,a1h,a2h,a3h);
        ldsm_x4(aAl + ck*32, a0l,a1l,a2l,a3l);
        ldsm_x4(aBh + ck*32, p0h,p1h,q0h,q1h);
        ldsm_x4(aBl + ck*32, p0l,p1l,q0l,q1l);
        mmabf(acc[0], a0h,a1h,a2h,a3h, p0h,p1h);
        mmabf(acc[0], a0l,a1l,a2l,a3l, p0h,p1h);
        mmabf(acc[0], a0h,a1h,a2h,a3h, p0l,p1l);
        mmabf(acc[1], a0h,a1h,a2h,a3h, q0h,q1h);
        mmabf(acc[1], a0l,a1l,a2l,a3l, q0h,q1h);
        mmabf(acc[1], a0h,a1h,a2h,a3h, q0l,q1l);
    }
}

// acc[4][4] += A(16 rows @ar0) x B^T(32 cols @n0*8): A loaded ONCE per ck
__device__ __forceinline__ void gemm16_n4(
    const uint32_t* __restrict__ Ah, const uint32_t* __restrict__ Al, int ar0,
    const uint32_t* __restrict__ Bh, const uint32_t* __restrict__ Bl, int n0,
    int lane, float (*acc)[4])
{
    const int la = lane & 7, l8 = (lane >> 3) & 1, l16 = lane >> 4;
    uint32_t aAh = smem_u32(Ah + (ar0 + la + l8*8)*SW) + l16*16;
    uint32_t aAl = smem_u32(Al + (ar0 + la + l8*8)*SW) + l16*16;
    uint32_t b0h = smem_u32(Bh + ((n0   + l16)*8 + la)*SW) + l8*16;
    uint32_t b1h = smem_u32(Bh + ((n0+2 + l16)*8 + la)*SW) + l8*16;
    uint32_t b0l = smem_u32(Bl + ((n0   + l16)*8 + la)*SW) + l8*16;
    uint32_t b1l = smem_u32(Bl + ((n0+2 + l16)*8 + la)*SW) + l8*16;
    #pragma unroll
    for (int ck = 0; ck < 4; ++ck) {
        uint32_t a0h,a1h,a2h,a3h, a0l,a1l,a2l,a3l;
        uint32_t p0,p1,q0,q1, r0,r1,s0,s1, P0,P1,Q0,Q1, R0,R1,S0,S1;
        ldsm_x4(aAh + ck*32, a0h,a1h,a2h,a3h);
        ldsm_x4(aAl + ck*32, a0l,a1l,a2l,a3l);
        ldsm_x4(b0h + ck*32, p0,p1,q0,q1);
        ldsm_x4(b1h + ck*32, r0,r1,s0,s1);
        ldsm_x4(b0l + ck*32, P0,P1,Q0,Q1);
        ldsm_x4(b1l + ck*32, R0,R1,S0,S1);
        mmabf(acc[0], a0h,a1h,a2h,a3h, p0,p1);
        mmabf(acc[0], a0l,a1l,a2l,a3l, p0,p1);
        mmabf(acc[0], a0h,a1h,a2h,a3h, P0,P1);
        mmabf(acc[1], a0h,a1h,a2h,a3h, q0,q1);
        mmabf(acc[1], a0l,a1l,a2l,a3l, q0,q1);
        mmabf(acc[1], a0h,a1h,a2h,a3h, Q0,Q1);
        mmabf(acc[2], a0h,a1h,a2h,a3h, r0,r1);
        mmabf(acc[2], a0l,a1l,a2l,a3l, r0,r1);
        mmabf(acc[2], a0h,a1h,a2h,a3h, R0,R1);
        mmabf(acc[3], a0h,a1h,a2h,a3h, s0,s1);
        mmabf(acc[3], a0l,a1l,a2l,a3l, s0,s1);
        mmabf(acc[3], a0h,a1h,a2h,a3h, S0,S1);
    }
}

// Proj: acc[8][4] += A(16 rows) x B^T(64 cols)
__device__ __forceinline__ void gemm16_n8(
    const uint32_t* __restrict__ Ah, const uint32_t* __restrict__ Al, int ar0,
    const uint32_t* __restrict__ Bh, const uint32_t* __restrict__ Bl,
    int lane, float (*acc)[4])
{
    const int la = lane & 7, l8 = (lane >> 3) & 1, l16 = lane >> 4;
    uint32_t aAh = smem_u32(Ah + (ar0 + la + l8*8)*SW) + l16*16;
    uint32_t aAl = smem_u32(Al + (ar0 + la + l8*8)*SW) + l16*16;
    uint32_t aBh = smem_u32(Bh + ((l16)*8 + la)*SW) + l8*16;
    uint32_t aBl = smem_u32(Bl + ((l16)*8 + la)*SW) + l8*16;
    #pragma unroll
    for (int ck = 0; ck < 4; ++ck) {
        uint32_t a0h,a1h,a2h,a3h, a0l,a1l,a2l,a3l;
        ldsm_x4(aAh + ck*32, a0h,a1h,a2h,a3h);
        ldsm_x4(aAl + ck*32, a0l,a1l,a2l,a3l);
        #pragma unroll
        for (int p = 0; p < 4; ++p) {
            uint32_t p0h,p1h,q0h,q1h, p0l,p1l,q0l,q1l;
            ldsm_x4(aBh + p*2304 + ck*32, p0h,p1h,q0h,q1h);
            ldsm_x4(aBl + p*2304 + ck*32, p0l,p1l,q0l,q1l);
            mmabf(acc[2*p  ], a0h,a1h,a2h,a3h, p0h,p1h);
            mmabf(acc[2*p  ], a0l,a1l,a2l,a3l, p0h,p1h);
            mmabf(acc[2*p  ], a0h,a1h,a2h,a3h, p0l,p1l);
            mmabf(acc[2*p+1], a0h,a1h,a2h,a3h, q0h,q1h);
            mmabf(acc[2*p+1], a0l,a1l,a2l,a3l, q0h,q1h);
            mmabf(acc[2*p+1], a0h,a1h,a2h,a3h, q0l,q1l);
        }
    }
}

// ---------------------------------------------------------------------------
// Kernel 0: split Er into bf16 hi/lo planes
// ---------------------------------------------------------------------------
__global__ void er_prep(const float* __restrict__ Er)
{
    int i = blockIdx.x * blockDim.x + threadIdx.x;
    if (i < T_*H_) {
        __nv_bfloat16 h, l;
        bsplit(Er[i], h, l);
        g_erhi[i] = h; g_erlo[i] = l;
    }
}

// ---------------------------------------------------------------------------
// Kernel 1: FUSED QKV projection: one CTA computes all three matrices for its
// 128 rows (x loaded+split ONCE). sW holds 192 transposed rows.
// K pre-scaled by 0.125; V written transposed.
// ---------------------------------------------------------------------------
#define PXH 0        /* 128 x SW */
#define PXL 4608
#define PWH 9216     /* 192 x SW */
#define PWL 16128
#define PSMEM_FLOATS 23040
#define PSMEM_BYTES (PSMEM_FLOATS*4)

__global__ __launch_bounds__(256) void proj_kernel(
    const float* __restrict__ x,
    const float* __restrict__ Wq,
    const float* __restrict__ Wk,
    const float* __restrict__ Wv)
{
    extern __shared__ float sm[];
    uint32_t* sXH = (uint32_t*)(sm + PXH);
    uint32_t* sXL = (uint32_t*)(sm + PXL);
    uint32_t* sWH = (uint32_t*)(sm + PWH);
    uint32_t* sWL = (uint32_t*)(sm + PWL);

    const int tid  = threadIdx.x;
    const int w    = tid >> 5;
    const int lane = tid & 31;
    const int gid  = lane >> 2;
    const int tig  = lane & 3;
    const int row0 = blockIdx.x * 128;
    const float* Ws[3] = {Wq, Wk, Wv};

    float acc[24][4];
    #pragma unroll
    for (int n = 0; n < 24; ++n)
        #pragma unroll
        for (int j = 0; j < 4; ++j) acc[n][j] = 0.f;

    for (int kc = 0; kc < C_; kc += 64) {
        __syncthreads();
        {   // x tile 128x64 -> 2 bf16 planes (once per chunk)
            int rr = tid >> 1, c0 = (tid & 1) * 32;
            const float4* xp = (const float4*)&x[(size_t)(row0 + rr) * C_ + kc + c0];
            __nv_bfloat162* dh = (__nv_bfloat162*)&sXH[rr*SW + c0/2];
            __nv_bfloat162* dl = (__nv_bfloat162*)&sXL[rr*SW + c0/2];
            #pragma unroll
            for (int u = 0; u < 8; ++u) {
                float4 v = xp[u];
                __nv_bfloat16 h0,l0,h1,l1;
                bsplit(v.x, h0, l0); bsplit(v.y, h1, l1);
                __nv_bfloat162 th; th.x = h0; th.y = h1;
                __nv_bfloat162 tl; tl.x = l0; tl.y = l1;
                dh[u*2]   = th; dl[u*2]   = tl;
                bsplit(v.z, h0, l0); bsplit(v.w, h1, l1);
                th.x = h0; th.y = h1; tl.x = l0; tl.y = l1;
                dh[u*2+1] = th; dl[u*2+1] = tl;
            }
        }
        {   // all three W chunks, transpose+split -> 192 rows
            int c = tid >> 2, h0 = (tid & 3) * 16;
            __nv_bfloat16* wh = (__nv_bfloat16*)sWH;
            __nv_bfloat16* wl = (__nv_bfloat16*)sWL;
            #pragma unroll
            for (int mat = 0; mat < 3; ++mat) {
                const float4* wp = (const float4*)&Ws[mat][(size_t)(kc + c) * H_ + h0];
                #pragma unroll
                for (int u = 0; u < 4; ++u) {
                    float4 v = wp[u];
                    int h = mat*64 + h0 + u*4;
                    __nv_bfloat16 hb, lb;
                    bsplit(v.x, hb, lb); wh[(h+0)*(2*SW) + c] = hb; wl[(h+0)*(2*SW) + c] = lb;
                    bsplit(v.y, hb, lb); wh[(h+1)*(2*SW) + c] = hb; wl[(h+1)*(2*SW) + c] = lb;
                    bsplit(v.z, hb, lb); wh[(h+2)*(2*SW) + c] = hb; wl[(h+2)*(2*SW) + c] = lb;
                    bsplit(v.w, hb, lb); wh[(h+3)*(2*SW) + c] = hb; wl[(h+3)*(2*SW) + c] = lb;
                }
            }
        }
        __syncthreads();
        #pragma unroll
        for (int mat = 0; mat < 3; ++mat)
            gemm16_n8(sXH, sXL, w*16, sWH + mat*64*SW, sWL + mat*64*SW,
                      lane, acc + mat*8);
    }

    const int r = row0 + w*16 + gid;
    #pragma unroll
    for (int mat = 0; mat < 2; ++mat) {
        __nv_bfloat16* ghi = (mat == 0) ? g_qhi : g_khi;
        __nv_bfloat16* glo = (mat == 0) ? g_qlo : g_klo;
        const float sc = (mat == 0) ? 1.0f : 0.125f;
        #pragma unroll
        for (int n = 0; n < 8; ++n) {
            float* a = acc[mat*8 + n];
            int h0 = n*8 + 2*tig;
            __nv_bfloat16 h0b,l0b,h1b,l1b;
            bsplit(a[0]*sc, h0b, l0b); bsplit(a[1]*sc, h1b, l1b);
            __nv_bfloat162 th; th.x = h0b; th.y = h1b;
            __nv_bfloat162 tl; tl.x = l0b; tl.y = l1b;
            *(__nv_bfloat162*)&ghi[(size_t)r*H_ + h0] = th;
            *(__nv_bfloat162*)&glo[(size_t)r*H_ + h0] = tl;
            bsplit(a[2]*sc, h0b, l0b); bsplit(a[3]*sc, h1b, l1b);
            th.x = h0b; th.y = h1b; tl.x = l0b; tl.y = l1b;
            *(__nv_bfloat162*)&ghi[(size_t)(r+8)*H_ + h0] = th;
            *(__nv_bfloat162*)&glo[(size_t)(r+8)*H_ + h0] = tl;
        }
    }
    #pragma unroll
    for (int n = 0; n < 8; ++n) {
        float* a = acc[16 + n];
        int h0 = n*8 + 2*tig;
        #pragma unroll
        for (int rr = 0; rr < 2; ++rr) {
            int rg = r + rr*8;
            int b  = rg >> 11, t = rg & 2047;
            __nv_bfloat16 hb, lb;
            bsplit(a[rr*2], hb, lb);
            g_vthi[((size_t)b*H_ + h0    )*T_ + t] = hb;
            g_vtlo[((size_t)b*H_ + h0    )*T_ + t] = lb;
            bsplit(a[rr*2+1], hb, lb);
            g_vthi[((size_t)b*H_ + h0 + 1)*T_ + t] = hb;
            g_vtlo[((size_t)b*H_ + h0 + 1)*T_ + t] = lb;
        }
    }
}

// ---------------------------------------------------------------------------
// Kernel 2: attention, 128-row tiles + E ring buffer (64 new rows/iter).
// 512 threads, 16 warps: wr=w&7 (16 rows), wg=w>>3 (32-col half).
// sE = 3 blocks of 64 rows (ring): logical block lb at iter jt lives in
// phys block (pb0 + lb) % 3, pb0 = (-jt) mod 3. Per iter only logical
// block 0 (lowest e) is loaded. P aliases the dead K+Qc region.
// ---------------------------------------------------------------------------
#define AQH   0        /* 128 x SW */
#define AQL   4608
#define AKH   9216     /* 64 x SW; P hi aliases [9216,13824) */
#define AKL   11520
#define AQCH  13824    /* P lo aliases [13824,18432) */
#define AQCL  16128
#define AVH   18432
#define AVL   20736
#define AEH   23040    /* 192 x SW ring */
#define AEL   29952
#define AGD   36864    /* 128 x 68 fp32 diagonal G */
#define ADIAG 45568
#define ASUM  45696    /* 2 x 128 */
#define ASMEM_FLOATS 45952
#define ASMEM_BYTES (ASMEM_FLOATS*4)

__global__ __launch_bounds__(512) void attn_kernel(
    const float* __restrict__ Er,
    float* __restrict__ out)
{
    extern __shared__ float sm[];
    uint32_t* sQH  = (uint32_t*)(sm + AQH);
    uint32_t* sQL  = (uint32_t*)(sm + AQL);
    uint32_t* sKH  = (uint32_t*)(sm + AKH);
    uint32_t* sKL  = (uint32_t*)(sm + AKL);
    uint32_t* sQCH = (uint32_t*)(sm + AQCH);
    uint32_t* sQCL = (uint32_t*)(sm + AQCL);
    uint32_t* sVH  = (uint32_t*)(sm + AVH);
    uint32_t* sVL  = (uint32_t*)(sm + AVL);
    uint32_t* sEH  = (uint32_t*)(sm + AEH);
    uint32_t* sEL  = (uint32_t*)(sm + AEL);
    uint32_t* sPH  = (uint32_t*)(sm + AKH);    // alias over K+Qc (dead by bar 3)
    uint32_t* sPL  = (uint32_t*)(sm + AQCH);
    float*    sGd  = sm + AGD;
    float*    sDiag= sm + ADIAG;
    float*    sSum = sm + ASUM;

    const int tid  = threadIdx.x;
    const int w    = tid >> 5;
    const int lane = tid & 31;
    const int gid  = lane >> 2;
    const int tig  = lane & 3;
    const int wr   = w & 7;
    const int wg   = w >> 3;
    const int b    = blockIdx.x;               // batch
    const int mm   = 15 - (int)blockIdx.y;     // big tiles launch first
    const int t0   = mm * 128;
    const size_t bT = (size_t)b * T_;
    const int r0   = wr*16 + gid;

    const int frr = tid >> 3;           // 64-row fill index
    const int fh8 = tid & 7;            // 8 x 16B segments

    uint4 z = make_uint4(0u,0u,0u,0u);

    {   // prologue: Q planes (128 rows) + E ring blocks 1,2 (phys 1,2)
        #pragma unroll
        for (int k = 0; k < 2; ++k) {
            int lin = tid + k*512;
            int rr = lin >> 3, sg = lin & 7;
            *(uint4*)&sQH[rr*SW + sg*4] =
                *(const uint4*)&g_qhi[(bT + t0 + rr)*H_ + sg*8];
            *(uint4*)&sQL[rr*SW + sg*4] =
                *(const uint4*)&g_qlo[(bT + t0 + rr)*H_ + sg*8];
            int e = t0 - 1 + rr;               // a = 64 + rr
            uint4 vh = z, vl = z;
            if (e >= 0) {
                vh = *(const uint4*)&g_erhi[(size_t)e*H_ + sg*8];
                vl = *(const uint4*)&g_erlo[(size_t)e*H_ + sg*8];
            }
            *(uint4*)&sEH[(64 + rr)*SW + sg*4] = vh;
            *(uint4*)&sEL[(64 + rr)*SW + sg*4] = vl;
        }
    }
    __syncthreads();

    {   // diag[r] = q[t0+r] . Er[T-1], 128 rows (4 threads/row)
        int r = tid >> 2, qd = tid & 3;
        const float* er = Er + (size_t)(T_-1) * H_;
        const __nv_bfloat16* qh = (const __nv_bfloat16*)sQH;
        const __nv_bfloat16* ql = (const __nv_bfloat16*)sQL;
        float p = 0.f;
        #pragma unroll
        for (int hh = 0; hh < 16; ++hh) {
            int h = qd*16 + hh;
            float qv = __bfloat162float(qh[r*(2*SW) + h]) +
                       __bfloat162float(ql[r*(2*SW) + h]);
            p += qv * er[h];
        }
        p += __shfl_xor_sync(0xffffffffu, p, 1);
        p += __shfl_xor_sync(0xffffffffu, p, 2);
        if (qd == 0) sDiag[r] = p;
    }

    float o[4][4];
    float lr0 = 0.f, lr1 = 0.f;
    #pragma unroll
    for (int n = 0; n < 4; ++n)
        #pragma unroll
        for (int j = 0; j < 4; ++j) o[n][j] = 0.f;

    const int n_iter = 2*mm + 2;
    int pb0 = 0;                           // (-jt) mod 3
    for (int jt = 0; jt < n_iter; ++jt) {
        const int s0 = jt * 64;
        const int d  = t0 - s0;            // >= -64

        // prefetch K/V/Qc + new E block gmem -> regs (overlaps barrier wait)
        uint4 pkh = *(const uint4*)&g_khi[(bT + s0 + frr)*H_ + fh8*8];
        uint4 pkl = *(const uint4*)&g_klo[(bT + s0 + frr)*H_ + fh8*8];
        uint4 pvh = *(const uint4*)&g_vthi[((size_t)b*H_ + frr)*T_ + s0 + fh8*8];
        uint4 pvl = *(const uint4*)&g_vtlo[((size_t)b*H_ + frr)*T_ + s0 + fh8*8];
        int qr = s0 + 1 + frr;
        uint4 pqh = z, pql = z;
        if (qr < T_) {
            pqh = *(const uint4*)&g_qhi[(bT + qr)*H_ + fh8*8];
            pql = *(const uint4*)&g_qlo[(bT + qr)*H_ + fh8*8];
        }
        int e = d - 65 + frr;              // logical block 0 row
        uint4 peh = z, pel = z;
        if (e >= 0) {
            peh = *(const uint4*)&g_erhi[(size_t)e*H_ + fh8*8];
            pel = *(const uint4*)&g_erlo[(size_t)e*H_ + fh8*8];
        }

        __syncthreads();   // (1) prev PV done; tiles free

        *(uint4*)&sKH[frr*SW + fh8*4] = pkh;
        *(uint4*)&sKL[frr*SW + fh8*4] = pkl;
        *(uint4*)&sQCH[frr*SW + fh8*4] = pqh;
        *(uint4*)&sQCL[frr*SW + fh8*4] = pql;
        *(uint4*)&sVH[frr*SW + fh8*4] = pvh;
        *(uint4*)&sVL[frr*SW + fh8*4] = pvl;
        *(uint4*)&sEH[(pb0*64 + frr)*SW + fh8*4] = peh;
        *(uint4*)&sEL[(pb0*64 + frr)*SW + fh8*4] = pel;
        __syncthreads();   // (2) tiles ready

        // G: 36 16x16 segments (ring-remapped A rows), diagonal scatter
        for (int si = w; si < 36; si += 16) {
            int seg = G_SEGS[si];
            int ta = seg >> 3, c16 = seg & 7;
            int pb = pb0 + (ta >> 2); if (pb >= 3) pb -= 3;
            int abase = pb*64 + (ta & 3)*16;
            float g[2][4];
            #pragma unroll
            for (int n = 0; n < 2; ++n)
                #pragma unroll
                for (int j = 0; j < 4; ++j) g[n][j] = 0.f;
            gemm16(sEH, sEL, abase, sQCH, sQCL, c16*2, lane, g);
            int ar = ta*16 + gid;
            #pragma unroll
            for (int n = 0; n < 2; ++n) {
                int cb = (c16*2+n)*8 + 2*tig;
                int rr;
                rr = ar + cb - 63;
                if ((unsigned)rr < 128u) sGd[rr*68 + cb]     = g[n][0];
                rr = ar + cb - 62;
                if ((unsigned)rr < 128u) sGd[rr*68 + cb + 1] = g[n][1];
                rr = ar + cb - 55;
                if ((unsigned)rr < 128u) sGd[rr*68 + cb]     = g[n][2];
                rr = ar + cb - 54;
                if ((unsigned)rr < 128u) sGd[rr*68 + cb + 1] = g[n][3];
            }
        }

        // S = Q x K^T (16 rows x 32 cols per warp)
        float s[4][4];
        #pragma unroll
        for (int n = 0; n < 4; ++n)
            #pragma unroll
            for (int j = 0; j < 4; ++j) s[n][j] = 0.f;
        gemm16_n4(sQH, sQL, wr*16, sKH, sKL, wg*4, lane, s);
        __syncthreads();   // (3) sGd complete; K/Qc dead -> P region free

        // assemble + exp + P store
        const bool dt = (d < 64);
        const int cd0 = r0 + d, cd1 = r0 + 8 + d;
        __nv_bfloat16* pH = (__nv_bfloat16*)sPH;
        __nv_bfloat16* pL = (__nv_bfloat16*)sPL;
        #pragma unroll
        for (int n = 0; n < 4; ++n) {
            int c0 = (wg*4+n)*8 + 2*tig;
            float2 gd0 = *(const float2*)&sGd[ r0   *68 + c0];
            float2 gd1 = *(const float2*)&sGd[(r0+8)*68 + c0];
            float v0 = s[n][0] + gd0.x;
            float v1 = s[n][1] + gd0.y;
            float v2 = s[n][2] + gd1.x;
            float v3 = s[n][3] + gd1.y;
            if (dt) {
                if (c0     > cd0) v0 = -3.0e38f; else if (c0     == cd0) v0 += sDiag[r0];
                if (c0 + 1 > cd0) v1 = -3.0e38f; else if (c0 + 1 == cd0) v1 += sDiag[r0];
                if (c0     > cd1) v2 = -3.0e38f; else if (c0     == cd1) v2 += sDiag[r0+8];
                if (c0 + 1 > cd1) v3 = -3.0e38f; else if (c0 + 1 == cd1) v3 += sDiag[r0+8];
            }
            float p0 = __expf(v0), p1 = __expf(v1);
            float p2 = __expf(v2), p3 = __expf(v3);
            lr0 += p0 + p1;
            lr1 += p2 + p3;
            __nv_bfloat16 h0b,l0b,h1b,l1b;
            bsplit(p0, h0b, l0b); bsplit(p1, h1b, l1b);
            __nv_bfloat162 th; th.x = h0b; th.y = h1b;
            __nv_bfloat162 tl; tl.x = l0b; tl.y = l1b;
            *(__nv_bfloat162*)&pH[r0*(2*SW) + c0] = th;
            *(__nv_bfloat162*)&pL[r0*(2*SW) + c0] = tl;
            bsplit(p2, h0b, l0b); bsplit(p3, h1b, l1b);
            th.x = h0b; th.y = h1b; tl.x = l0b; tl.y = l1b;
            *(__nv_bfloat162*)&pH[(r0+8)*(2*SW) + c0] = th;
            *(__nv_bfloat162*)&pL[(r0+8)*(2*SW) + c0] = tl;
        }
        __syncthreads();   // (4) sP complete

        // O += P x V^T (16 rows x 32 h-cols per warp)
        gemm16_n4(sPH, sPL, wr*16, sVH, sVL, wg*4, lane, o);

        pb0 -= 1; if (pb0 < 0) pb0 = 2;    // pb0 = (-jt) mod 3
    }

    // final denominator reduce
    lr0 += __shfl_xor_sync(0xffffffffu, lr0, 1);
    lr0 += __shfl_xor_sync(0xffffffffu, lr0, 2);
    lr1 += __shfl_xor_sync(0xffffffffu, lr1, 1);
    lr1 += __shfl_xor_sync(0xffffffffu, lr1, 2);
    if (tig == 0) {
        sSum[wg*128 + r0]     = lr0;
        sSum[wg*128 + r0 + 8] = lr1;
    }
    __syncthreads();
    float tl0 = sSum[r0]     + sSum[128 + r0];
    float tl1 = sSum[r0 + 8] + sSum[128 + r0 + 8];
    float inv0 = 1.f / tl0;
    float inv1 = 1.f / tl1;
    #pragma unroll
    for (int n = 0; n < 4; ++n) {
        int c0 = (wg*4+n)*8 + 2*tig;
        *(float2*)&out[(bT + t0 + r0    )*H_ + c0] =
            make_float2(o[n][0]*inv0, o[n][1]*inv0);
        *(float2*)&out[(bT + t0 + r0 + 8)*H_ + c0] =
            make_float2(o[n][2]*inv1, o[n][3]*inv1);
    }
}

// ---------------------------------------------------------------------------
extern "C" void kernel_launch(void* const* d_in, const int* in_sizes, int n_in,
                              void* d_out, int out_size)
{
    const float* x  = (const float*)d_in[0];
    const float* Wq = (const float*)d_in[1];
    const float* Wk = (const float*)d_in[2];
    const float* Wv = (const float*)d_in[3];
    const float* Er = (const float*)d_in[4];
    float* out = (float*)d_out;

    cudaFuncSetAttribute(proj_kernel,
                         cudaFuncAttributeMaxDynamicSharedMemorySize, PSMEM_BYTES);
    cudaFuncSetAttribute(attn_kernel,
                         cudaFuncAttributeMaxDynamicSharedMemorySize, ASMEM_BYTES);

    er_prep<<<(T_*H_ + 255)/256, 256>>>(Er);
    proj_kernel<<<256, 256, PSMEM_BYTES>>>(x, Wq, Wk, Wv);
    attn_kernel<<<dim3(16, 16), 512, ASMEM_BYTES>>>(Er, out);
}

// round 14
// speedup vs baseline: 1.4206x; 1.4206x over previous
#include <cuda_runtime.h>
#include <cuda_bf16.h>
#include <math.h>
#include <stdint.h>

#define B_ 16
#define T_ 2048
#define C_ 512
#define H_ 64
#define SW 36   /* smem plane row stride in 32-bit words (72 bf16, 144 B) */

// Global scratch: bf16 hi/lo planes (allowed __device__ scratch path)
__device__ __nv_bfloat16 g_qhi[B_*T_*H_], g_qlo[B_*T_*H_];
__device__ __nv_bfloat16 g_khi[B_*T_*H_], g_klo[B_*T_*H_];   // pre-scaled by 0.125
__device__ __nv_bfloat16 g_vthi[B_*H_*T_], g_vtlo[B_*H_*T_]; // [b][h][t]
__device__ __nv_bfloat16 g_erhi[T_*H_], g_erlo[T_*H_];

// 36 used 16x16 G segments for the 128-row tile: value = ta*8 + c16
__constant__ unsigned char G_SEGS[36] = {
    24,17,10,3,  32,25,18,11,  40,33,26,19,  48,41,34,27,
    56,49,42,35, 64,57,50,43,  72,65,58,51,  80,73,66,59,
    88,81,74,67
};

// ---------------------------------------------------------------------------
// helpers
// ---------------------------------------------------------------------------
__device__ __forceinline__ void bsplit(float x, __nv_bfloat16& h, __nv_bfloat16& l) {
    h = __float2bfloat16_rn(x);
    l = __float2bfloat16_rn(x - __bfloat162float(h));
}
__device__ __forceinline__ uint32_t smem_u32(const void* p) {
    return (uint32_t)__cvta_generic_to_shared(p);
}
__device__ __forceinline__ void ldsm_x4(uint32_t addr,
    uint32_t& r0, uint32_t& r1, uint32_t& r2, uint32_t& r3)
{
    asm volatile("ldmatrix.sync.aligned.m8n8.x4.shared.b16 {%0,%1,%2,%3}, [%4];"
        : "=r"(r0), "=r"(r1), "=r"(r2), "=r"(r3) : "r"(addr));
}
__device__ __forceinline__ void mmabf(float* c,
    uint32_t a0, uint32_t a1, uint32_t a2, uint32_t a3, uint32_t b0, uint32_t b1)
{
    asm volatile(
        "mma.sync.aligned.m16n8k16.row.col.f32.bf16.bf16.f32 "
        "{%0,%1,%2,%3}, {%4,%5,%6,%7}, {%8,%9}, {%0,%1,%2,%3};"
        : "+f"(c[0]), "+f"(c[1]), "+f"(c[2]), "+f"(c[3])
        : "r"(a0), "r"(a1), "r"(a2), "r"(a3), "r"(b0), "r"(b1));
}

// acc[2][4] += A(16 rows @ar0, 2-plane) x B^T(16 cols @n0*8, 2-plane)
__device__ __forceinline__ void gemm16(
    const uint32_t* __restrict__ Ah, const uint32_t* __restrict__ Al, int ar0,
    const uint32_t* __restrict__ Bh, const uint32_t* __restrict__ Bl, int n0,
    int lane, float (*acc)[4])
{
    const int la = lane & 7, l8 = (lane >> 3) & 1, l16 = lane >> 4;
    uint32_t aAh = smem_u32(Ah + (ar0 + la + l8*8)*SW) + l16*16;
    uint32_t aAl = smem_u32(Al + (ar0 + la + l8*8)*SW) + l16*16;
    uint32_t aBh = smem_u32(Bh + ((n0 + l16)*8 + la)*SW) + l8*16;
    uint32_t aBl = smem_u32(Bl + ((n0 + l16)*8 + la)*SW) + l8*16;
    #pragma unroll
    for (int ck = 0; ck < 4; ++ck) {
        uint32_t a0h,a1h,a2h,a3h, a0l,a1l,a2l,a3l;
        uint32_t p0h,p1h,q0h,q1h, p0l,p1l,q0l,q1l;
        ldsm_x4(aAh + ck*32, a0h,a1h,a2h,a3h);
        ldsm_x4(aAl + ck*32, a0l,a1l,a2l,a3l);
        ldsm_x4(aBh + ck*32, p0h,p1h,q0h,q1h);
        ldsm_x4(aBl + ck*32, p0l,p1l,q0l,q1l);
        mmabf(acc[0], a0h,a1h,a2h,a3h, p0h,p1h);
        mmabf(acc[0], a0l,a1l,a2l,a3l, p0h,p1h);
        mmabf(acc[0], a0h,a1h,a2h,a3h, p0l,p1l);
        mmabf(acc[1], a0h,a1h,a2h,a3h, q0h,q1h);
        mmabf(acc[1], a0l,a1l,a2l,a3l, q0h,q1h);
        mmabf(acc[1], a0h,a1h,a2h,a3h, q0l,q1l);
    }
}

// acc[4][4] += A(16 rows @ar0) x B^T(32 cols @n0*8): A loaded ONCE per ck
__device__ __forceinline__ void gemm16_n4(
    const uint32_t* __restrict__ Ah, const uint32_t* __restrict__ Al, int ar0,
    const uint32_t* __restrict__ Bh, const uint32_t* __restrict__ Bl, int n0,
    int lane, float (*acc)[4])
{
    const int la = lane & 7, l8 = (lane >> 3) & 1, l16 = lane >> 4;
    uint32_t aAh = smem_u32(Ah + (ar0 + la + l8*8)*SW) + l16*16;
    uint32_t aAl = smem_u32(Al + (ar0 + la + l8*8)*SW) + l16*16;
    uint32_t b0h = smem_u32(Bh + ((n0   + l16)*8 + la)*SW) + l8*16;
    uint32_t b1h = smem_u32(Bh + ((n0+2 + l16)*8 + la)*SW) + l8*16;
    uint32_t b0l = smem_u32(Bl + ((n0   + l16)*8 + la)*SW) + l8*16;
    uint32_t b1l = smem_u32(Bl + ((n0+2 + l16)*8 + la)*SW) + l8*16;
    #pragma unroll
    for (int ck = 0; ck < 4; ++ck) {
        uint32_t a0h,a1h,a2h,a3h, a0l,a1l,a2l,a3l;
        uint32_t p0,p1,q0,q1, r0,r1,s0,s1, P0,P1,Q0,Q1, R0,R1,S0,S1;
        ldsm_x4(aAh + ck*32, a0h,a1h,a2h,a3h);
        ldsm_x4(aAl + ck*32, a0l,a1l,a2l,a3l);
        ldsm_x4(b0h + ck*32, p0,p1,q0,q1);
        ldsm_x4(b1h + ck*32, r0,r1,s0,s1);
        ldsm_x4(b0l + ck*32, P0,P1,Q0,Q1);
        ldsm_x4(b1l + ck*32, R0,R1,S0,S1);
        mmabf(acc[0], a0h,a1h,a2h,a3h, p0,p1);
        mmabf(acc[0], a0l,a1l,a2l,a3l, p0,p1);
        mmabf(acc[0], a0h,a1h,a2h,a3h, P0,P1);
        mmabf(acc[1], a0h,a1h,a2h,a3h, q0,q1);
        mmabf(acc[1], a0l,a1l,a2l,a3l, q0,q1);
        mmabf(acc[1], a0h,a1h,a2h,a3h, Q0,Q1);
        mmabf(acc[2], a0h,a1h,a2h,a3h, r0,r1);
        mmabf(acc[2], a0l,a1l,a2l,a3l, r0,r1);
        mmabf(acc[2], a0h,a1h,a2h,a3h, R0,R1);
        mmabf(acc[3], a0h,a1h,a2h,a3h, s0,s1);
        mmabf(acc[3], a0l,a1l,a2l,a3l, s0,s1);
        mmabf(acc[3], a0h,a1h,a2h,a3h, S0,S1);
    }
}

// Proj: acc[8][4] += A(16 rows) x B^T(64 cols)
__device__ __forceinline__ void gemm16_n8(
    const uint32_t* __restrict__ Ah, const uint32_t* __restrict__ Al, int ar0,
    const uint32_t* __restrict__ Bh, const uint32_t* __restrict__ Bl,
    int lane, float (*acc)[4])
{
    const int la = lane & 7, l8 = (lane >> 3) & 1, l16 = lane >> 4;
    uint32_t aAh = smem_u32(Ah + (ar0 + la + l8*8)*SW) + l16*16;
    uint32_t aAl = smem_u32(Al + (ar0 + la + l8*8)*SW) + l16*16;
    uint32_t aBh = smem_u32(Bh + ((l16)*8 + la)*SW) + l8*16;
    uint32_t aBl = smem_u32(Bl + ((l16)*8 + la)*SW) + l8*16;
    #pragma unroll
    for (int ck = 0; ck < 4; ++ck) {
        uint32_t a0h,a1h,a2h,a3h, a0l,a1l,a2l,a3l;
        ldsm_x4(aAh + ck*32, a0h,a1h,a2h,a3h);
        ldsm_x4(aAl + ck*32, a0l,a1l,a2l,a3l);
        #pragma unroll
        for (int p = 0; p < 4; ++p) {
            uint32_t p0h,p1h,q0h,q1h, p0l,p1l,q0l,q1l;
            ldsm_x4(aBh + p*2304 + ck*32, p0h,p1h,q0h,q1h);
            ldsm_x4(aBl + p*2304 + ck*32, p0l,p1l,q0l,q1l);
            mmabf(acc[2*p  ], a0h,a1h,a2h,a3h, p0h,p1h);
            mmabf(acc[2*p  ], a0l,a1l,a2l,a3l, p0h,p1h);
            mmabf(acc[2*p  ], a0h,a1h,a2h,a3h, p0l,p1l);
            mmabf(acc[2*p+1], a0h,a1h,a2h,a3h, q0h,q1h);
            mmabf(acc[2*p+1], a0l,a1l,a2l,a3l, q0h,q1h);
            mmabf(acc[2*p+1], a0h,a1h,a2h,a3h, q0l,q1l);
        }
    }
}

// ---------------------------------------------------------------------------
// Kernel 0: split Er into bf16 hi/lo planes
// ---------------------------------------------------------------------------
__global__ void er_prep(const float* __restrict__ Er)
{
    int i = blockIdx.x * blockDim.x + threadIdx.x;
    if (i < T_*H_) {
        __nv_bfloat16 h, l;
        bsplit(Er[i], h, l);
        g_erhi[i] = h; g_erlo[i] = l;
    }
}

// ---------------------------------------------------------------------------
// Kernel 1: QKV projection — R11's proven per-matrix version (one W per
// blockIdx.y, acc[8][4], no spills). K pre-scaled by 0.125; V transposed.
// ---------------------------------------------------------------------------
#define PXH 0
#define PXL 4608
#define PWH 9216
#define PWL 11520
#define PSMEM_FLOATS 13824
#define PSMEM_BYTES (PSMEM_FLOATS*4)

__global__ __launch_bounds__(256) void proj_kernel(
    const float* __restrict__ x,
    const float* __restrict__ Wq,
    const float* __restrict__ Wk,
    const float* __restrict__ Wv)
{
    extern __shared__ float sm[];
    uint32_t* sXH = (uint32_t*)(sm + PXH);
    uint32_t* sXL = (uint32_t*)(sm + PXL);
    uint32_t* sWH = (uint32_t*)(sm + PWH);
    uint32_t* sWL = (uint32_t*)(sm + PWL);

    const int tid  = threadIdx.x;
    const int w    = tid >> 5;
    const int lane = tid & 31;
    const int gid  = lane >> 2;
    const int tig  = lane & 3;
    const int row0 = blockIdx.x * 128;
    const int mat  = blockIdx.y;
    const float* __restrict__ W = (mat == 0) ? Wq : (mat == 1) ? Wk : Wv;

    float acc[8][4];
    #pragma unroll
    for (int n = 0; n < 8; ++n)
        #pragma unroll
        for (int j = 0; j < 4; ++j) acc[n][j] = 0.f;

    for (int kc = 0; kc < C_; kc += 64) {
        __syncthreads();
        {
            int rr = tid >> 1, c0 = (tid & 1) * 32;
            const float4* xp = (const float4*)&x[(size_t)(row0 + rr) * C_ + kc + c0];
            __nv_bfloat162* dh = (__nv_bfloat162*)&sXH[rr*SW + c0/2];
            __nv_bfloat162* dl = (__nv_bfloat162*)&sXL[rr*SW + c0/2];
            #pragma unroll
            for (int u = 0; u < 8; ++u) {
                float4 v = xp[u];
                __nv_bfloat16 h0,l0,h1,l1;
                bsplit(v.x, h0, l0); bsplit(v.y, h1, l1);
                __nv_bfloat162 th; th.x = h0; th.y = h1;
                __nv_bfloat162 tl; tl.x = l0; tl.y = l1;
                dh[u*2]   = th; dl[u*2]   = tl;
                bsplit(v.z, h0, l0); bsplit(v.w, h1, l1);
                th.x = h0; th.y = h1; tl.x = l0; tl.y = l1;
                dh[u*2+1] = th; dl[u*2+1] = tl;
            }
        }
        {
            int c = tid >> 2, h0 = (tid & 3) * 16;
            __nv_bfloat16* wh = (__nv_bfloat16*)sWH;
            __nv_bfloat16* wl = (__nv_bfloat16*)sWL;
            const float4* wp = (const float4*)&W[(size_t)(kc + c) * H_ + h0];
            #pragma unroll
            for (int u = 0; u < 4; ++u) {
                float4 v = wp[u];
                int h = h0 + u*4;
                __nv_bfloat16 hb, lb;
                bsplit(v.x, hb, lb); wh[(h+0)*(2*SW) + c] = hb; wl[(h+0)*(2*SW) + c] = lb;
                bsplit(v.y, hb, lb); wh[(h+1)*(2*SW) + c] = hb; wl[(h+1)*(2*SW) + c] = lb;
                bsplit(v.z, hb, lb); wh[(h+2)*(2*SW) + c] = hb; wl[(h+2)*(2*SW) + c] = lb;
                bsplit(v.w, hb, lb); wh[(h+3)*(2*SW) + c] = hb; wl[(h+3)*(2*SW) + c] = lb;
            }
        }
        __syncthreads();
        gemm16_n8(sXH, sXL, w*16, sWH, sWL, lane, acc);
    }

    const int r = row0 + w*16 + gid;
    if (mat < 2) {
        __nv_bfloat16* ghi = (mat == 0) ? g_qhi : g_khi;
        __nv_bfloat16* glo = (mat == 0) ? g_qlo : g_klo;
        const float sc = (mat == 0) ? 1.0f : 0.125f;
        #pragma unroll
        for (int n = 0; n < 8; ++n) {
            int h0 = n*8 + 2*tig;
            __nv_bfloat16 h0b,l0b,h1b,l1b;
            bsplit(acc[n][0]*sc, h0b, l0b); bsplit(acc[n][1]*sc, h1b, l1b);
            __nv_bfloat162 th; th.x = h0b; th.y = h1b;
            __nv_bfloat162 tl; tl.x = l0b; tl.y = l1b;
            *(__nv_bfloat162*)&ghi[(size_t)r*H_ + h0] = th;
            *(__nv_bfloat162*)&glo[(size_t)r*H_ + h0] = tl;
            bsplit(acc[n][2]*sc, h0b, l0b); bsplit(acc[n][3]*sc, h1b, l1b);
            th.x = h0b; th.y = h1b; tl.x = l0b; tl.y = l1b;
            *(__nv_bfloat162*)&ghi[(size_t)(r+8)*H_ + h0] = th;
            *(__nv_bfloat162*)&glo[(size_t)(r+8)*H_ + h0] = tl;
        }
    } else {
        #pragma unroll
        for (int n = 0; n < 8; ++n) {
            int h0 = n*8 + 2*tig;
            #pragma unroll
            for (int rr = 0; rr < 2; ++rr) {
                int rg = r + rr*8;
                int b  = rg >> 11, t = rg & 2047;
                float v0 = acc[n][rr*2], v1 = acc[n][rr*2+1];
                __nv_bfloat16 hb, lb;
                bsplit(v0, hb, lb);
                g_vthi[((size_t)b*H_ + h0    )*T_ + t] = hb;
                g_vtlo[((size_t)b*H_ + h0    )*T_ + t] = lb;
                bsplit(v1, hb, lb);
                g_vthi[((size_t)b*H_ + h0 + 1)*T_ + t] = hb;
                g_vtlo[((size_t)b*H_ + h0 + 1)*T_ + t] = lb;
            }
        }
    }
}

// ---------------------------------------------------------------------------
// Kernel 2: attention (R13 version, unchanged): 128-row tiles + E ring.
// 512 threads, 16 warps: wr=w&7 (16 rows), wg=w>>3 (32-col half).
// sE = 3 blocks of 64 rows (ring); only logical block 0 loaded per iter.
// P aliases the dead K+Qc region after bar(3).
// ---------------------------------------------------------------------------
#define AQH   0        /* 128 x SW */
#define AQL   4608
#define AKH   9216     /* 64 x SW; P hi aliases [9216,13824) */
#define AKL   11520
#define AQCH  13824    /* P lo aliases [13824,18432) */
#define AQCL  16128
#define AVH   18432
#define AVL   20736
#define AEH   23040    /* 192 x SW ring */
#define AEL   29952
#define AGD   36864    /* 128 x 68 fp32 diagonal G */
#define ADIAG 45568
#define ASUM  45696    /* 2 x 128 */
#define ASMEM_FLOATS 45952
#define ASMEM_BYTES (ASMEM_FLOATS*4)

__global__ __launch_bounds__(512) void attn_kernel(
    const float* __restrict__ Er,
    float* __restrict__ out)
{
    extern __shared__ float sm[];
    uint32_t* sQH  = (uint32_t*)(sm + AQH);
    uint32_t* sQL  = (uint32_t*)(sm + AQL);
    uint32_t* sKH  = (uint32_t*)(sm + AKH);
    uint32_t* sKL  = (uint32_t*)(sm + AKL);
    uint32_t* sQCH = (uint32_t*)(sm + AQCH);
    uint32_t* sQCL = (uint32_t*)(sm + AQCL);
    uint32_t* sVH  = (uint32_t*)(sm + AVH);
    uint32_t* sVL  = (uint32_t*)(sm + AVL);
    uint32_t* sEH  = (uint32_t*)(sm + AEH);
    uint32_t* sEL  = (uint32_t*)(sm + AEL);
    uint32_t* sPH  = (uint32_t*)(sm + AKH);    // alias over K+Qc (dead by bar 3)
    uint32_t* sPL  = (uint32_t*)(sm + AQCH);
    float*    sGd  = sm + AGD;
    float*    sDiag= sm + ADIAG;
    float*    sSum = sm + ASUM;

    const int tid  = threadIdx.x;
    const int w    = tid >> 5;
    const int lane = tid & 31;
    const int gid  = lane >> 2;
    const int tig  = lane & 3;
    const int wr   = w & 7;
    const int wg   = w >> 3;
    const int b    = blockIdx.x;               // batch
    const int mm   = 15 - (int)blockIdx.y;     // big tiles launch first
    const int t0   = mm * 128;
    const size_t bT = (size_t)b * T_;
    const int r0   = wr*16 + gid;

    const int frr = tid >> 3;           // 64-row fill index
    const int fh8 = tid & 7;            // 8 x 16B segments

    uint4 z = make_uint4(0u,0u,0u,0u);

    {   // prologue: Q planes (128 rows) + E ring blocks 1,2 (phys 1,2)
        #pragma unroll
        for (int k = 0; k < 2; ++k) {
            int lin = tid + k*512;
            int rr = lin >> 3, sg = lin & 7;
            *(uint4*)&sQH[rr*SW + sg*4] =
                *(const uint4*)&g_qhi[(bT + t0 + rr)*H_ + sg*8];
            *(uint4*)&sQL[rr*SW + sg*4] =
                *(const uint4*)&g_qlo[(bT + t0 + rr)*H_ + sg*8];
            int e = t0 - 1 + rr;               // a = 64 + rr
            uint4 vh = z, vl = z;
            if (e >= 0) {
                vh = *(const uint4*)&g_erhi[(size_t)e*H_ + sg*8];
                vl = *(const uint4*)&g_erlo[(size_t)e*H_ + sg*8];
            }
            *(uint4*)&sEH[(64 + rr)*SW + sg*4] = vh;
            *(uint4*)&sEL[(64 + rr)*SW + sg*4] = vl;
        }
    }
    __syncthreads();

    {   // diag[r] = q[t0+r] . Er[T-1], 128 rows (4 threads/row)
        int r = tid >> 2, qd = tid & 3;
        const float* er = Er + (size_t)(T_-1) * H_;
        const __nv_bfloat16* qh = (const __nv_bfloat16*)sQH;
        const __nv_bfloat16* ql = (const __nv_bfloat16*)sQL;
        float p = 0.f;
        #pragma unroll
        for (int hh = 0; hh < 16; ++hh) {
            int h = qd*16 + hh;
            float qv = __bfloat162float(qh[r*(2*SW) + h]) +
                       __bfloat162float(ql[r*(2*SW) + h]);
            p += qv * er[h];
        }
        p += __shfl_xor_sync(0xffffffffu, p, 1);
        p += __shfl_xor_sync(0xffffffffu, p, 2);
        if (qd == 0) sDiag[r] = p;
    }

    float o[4][4];
    float lr0 = 0.f, lr1 = 0.f;
    #pragma unroll
    for (int n = 0; n < 4; ++n)
        #pragma unroll
        for (int j = 0; j < 4; ++j) o[n][j] = 0.f;

    const int n_iter = 2*mm + 2;
    int pb0 = 0;                           // (-jt) mod 3
    for (int jt = 0; jt < n_iter; ++jt) {
        const int s0 = jt * 64;
        const int d  = t0 - s0;            // >= -64

        // prefetch K/V/Qc + new E block gmem -> regs (overlaps barrier wait)
        uint4 pkh = *(const uint4*)&g_khi[(bT + s0 + frr)*H_ + fh8*8];
        uint4 pkl = *(const uint4*)&g_klo[(bT + s0 + frr)*H_ + fh8*8];
        uint4 pvh = *(const uint4*)&g_vthi[((size_t)b*H_ + frr)*T_ + s0 + fh8*8];
        uint4 pvl = *(const uint4*)&g_vtlo[((size_t)b*H_ + frr)*T_ + s0 + fh8*8];
        int qr = s0 + 1 + frr;
        uint4 pqh = z, pql = z;
        if (qr < T_) {
            pqh = *(const uint4*)&g_qhi[(bT + qr)*H_ + fh8*8];
            pql = *(const uint4*)&g_qlo[(bT + qr)*H_ + fh8*8];
        }
        int e = d - 65 + frr;              // logical block 0 row
        uint4 peh = z, pel = z;
        if (e >= 0) {
            peh = *(const uint4*)&g_erhi[(size_t)e*H_ + fh8*8];
            pel = *(const uint4*)&g_erlo[(size_t)e*H_ + fh8*8];
        }

        __syncthreads();   // (1) prev PV done; tiles free

        *(uint4*)&sKH[frr*SW + fh8*4] = pkh;
        *(uint4*)&sKL[frr*SW + fh8*4] = pkl;
        *(uint4*)&sQCH[frr*SW + fh8*4] = pqh;
        *(uint4*)&sQCL[frr*SW + fh8*4] = pql;
        *(uint4*)&sVH[frr*SW + fh8*4] = pvh;
        *(uint4*)&sVL[frr*SW + fh8*4] = pvl;
        *(uint4*)&sEH[(pb0*64 + frr)*SW + fh8*4] = peh;
        *(uint4*)&sEL[(pb0*64 + frr)*SW + fh8*4] = pel;
        __syncthreads();   // (2) tiles ready

        // G: 36 16x16 segments (ring-remapped A rows), diagonal scatter
        for (int si = w; si < 36; si += 16) {
            int seg = G_SEGS[si];
            int ta = seg >> 3, c16 = seg & 7;
            int pb = pb0 + (ta >> 2); if (pb >= 3) pb -= 3;
            int abase = pb*64 + (ta & 3)*16;
            float g[2][4];
            #pragma unroll
            for (int n = 0; n < 2; ++n)
                #pragma unroll
                for (int j = 0; j < 4; ++j) g[n][j] = 0.f;
            gemm16(sEH, sEL, abase, sQCH, sQCL, c16*2, lane, g);
            int ar = ta*16 + gid;
            #pragma unroll
            for (int n = 0; n < 2; ++n) {
                int cb = (c16*2+n)*8 + 2*tig;
                int rr;
                rr = ar + cb - 63;
                if ((unsigned)rr < 128u) sGd[rr*68 + cb]     = g[n][0];
                rr = ar + cb - 62;
                if ((unsigned)rr < 128u) sGd[rr*68 + cb + 1] = g[n][1];
                rr = ar + cb - 55;
                if ((unsigned)rr < 128u) sGd[rr*68 + cb]     = g[n][2];
                rr = ar + cb - 54;
                if ((unsigned)rr < 128u) sGd[rr*68 + cb + 1] = g[n][3];
            }
        }

        // S = Q x K^T (16 rows x 32 cols per warp)
        float s[4][4];
        #pragma unroll
        for (int n = 0; n < 4; ++n)
            #pragma unroll
            for (int j = 0; j < 4; ++j) s[n][j] = 0.f;
        gemm16_n4(sQH, sQL, wr*16, sKH, sKL, wg*4, lane, s);
        __syncthreads();   // (3) sGd complete; K/Qc dead -> P region free

        // assemble + exp + P store
        const bool dt = (d < 64);
        const int cd0 = r0 + d, cd1 = r0 + 8 + d;
        __nv_bfloat16* pH = (__nv_bfloat16*)sPH;
        __nv_bfloat16* pL = (__nv_bfloat16*)sPL;
        #pragma unroll
        for (int n = 0; n < 4; ++n) {
            int c0 = (wg*4+n)*8 + 2*tig;
            float2 gd0 = *(const float2*)&sGd[ r0   *68 + c0];
            float2 gd1 = *(const float2*)&sGd[(r0+8)*68 + c0];
            float v0 = s[n][0] + gd0.x;
            float v1 = s[n][1] + gd0.y;
            float v2 = s[n][2] + gd1.x;
            float v3 = s[n][3] + gd1.y;
            if (dt) {
                if (c0     > cd0) v0 = -3.0e38f; else if (c0     == cd0) v0 += sDiag[r0];
                if (c0 + 1 > cd0) v1 = -3.0e38f; else if (c0 + 1 == cd0) v1 += sDiag[r0];
                if (c0     > cd1) v2 = -3.0e38f; else if (c0     == cd1) v2 += sDiag[r0+8];
                if (c0 + 1 > cd1) v3 = -3.0e38f; else if (c0 + 1 == cd1) v3 += sDiag[r0+8];
            }
            float p0 = __expf(v0), p1 = __expf(v1);
            float p2 = __expf(v2), p3 = __expf(v3);
            lr0 += p0 + p1;
            lr1 += p2 + p3;
            __nv_bfloat16 h0b,l0b,h1b,l1b;
            bsplit(p0, h0b, l0b); bsplit(p1, h1b, l1b);
            __nv_bfloat162 th; th.x = h0b; th.y = h1b;
            __nv_bfloat162 tl; tl.x = l0b; tl.y = l1b;
            *(__nv_bfloat162*)&pH[r0*(2*SW) + c0] = th;
            *(__nv_bfloat162*)&pL[r0*(2*SW) + c0] = tl;
            bsplit(p2, h0b, l0b); bsplit(p3, h1b, l1b);
            th.x = h0b; th.y = h1b; tl.x = l0b; tl.y = l1b;
            *(__nv_bfloat162*)&pH[(r0+8)*(2*SW) + c0] = th;
            *(__nv_bfloat162*)&pL[(r0+8)*(2*SW) + c0] = tl;
        }
        __syncthreads();   // (4) sP complete

        // O += P x V^T (16 rows x 32 h-cols per warp)
        gemm16_n4(sPH, sPL, wr*16, sVH, sVL, wg*4, lane, o);

        pb0 -= 1; if (pb0 < 0) pb0 = 2;    // pb0 = (-jt) mod 3
    }

    // final denominator reduce
    lr0 += __shfl_xor_sync(0xffffffffu, lr0, 1);
    lr0 += __shfl_xor_sync(0xffffffffu, lr0, 2);
    lr1 += __shfl_xor_sync(0xffffffffu, lr1, 1);
    lr1 += __shfl_xor_sync(0xffffffffu, lr1, 2);
    if (tig == 0) {
        sSum[wg*128 + r0]     = lr0;
        sSum[wg*128 + r0 + 8] = lr1;
    }
    __syncthreads();
    float tl0 = sSum[r0]     + sSum[128 + r0];
    float tl1 = sSum[r0 + 8] + sSum[128 + r0 + 8];
    float inv0 = 1.f / tl0;
    float inv1 = 1.f / tl1;
    #pragma unroll
    for (int n = 0; n < 4; ++n) {
        int c0 = (wg*4+n)*8 + 2*tig;
        *(float2*)&out[(bT + t0 + r0    )*H_ + c0] =
            make_float2(o[n][0]*inv0, o[n][1]*inv0);
        *(float2*)&out[(bT + t0 + r0 + 8)*H_ + c0] =
            make_float2(o[n][2]*inv1, o[n][3]*inv1);
    }
}

// ---------------------------------------------------------------------------
extern "C" void kernel_launch(void* const* d_in, const int* in_sizes, int n_in,
                              void* d_out, int out_size)
{
    const float* x  = (const float*)d_in[0];
    const float* Wq = (const float*)d_in[1];
    const float* Wk = (const float*)d_in[2];
    const float* Wv = (const float*)d_in[3];
    const float* Er = (const float*)d_in[4];
    float* out = (float*)d_out;

    cudaFuncSetAttribute(proj_kernel,
                         cudaFuncAttributeMaxDynamicSharedMemorySize, PSMEM_BYTES);
    cudaFuncSetAttribute(attn_kernel,
                         cudaFuncAttributeMaxDynamicSharedMemorySize, ASMEM_BYTES);

    er_prep<<<(T_*H_ + 255)/256, 256>>>(Er);
    proj_kernel<<<dim3(256, 3), 256, PSMEM_BYTES>>>(x, Wq, Wk, Wv);
    attn_kernel<<<dim3(16, 16), 512, ASMEM_BYTES>>>(Er, out);
}

// round 15
// speedup vs baseline: 1.5271x; 1.0749x over previous
#include <cuda_runtime.h>
#include <cuda_bf16.h>
#include <math.h>
#include <stdint.h>

#define B_ 16
#define T_ 2048
#define C_ 512
#define H_ 64
#define SW 36   /* smem plane row stride in 32-bit words (72 bf16, 144 B) */

// Global scratch: bf16 hi/lo planes (allowed __device__ scratch path)
__device__ __nv_bfloat16 g_qhi[B_*T_*H_], g_qlo[B_*T_*H_];
__device__ __nv_bfloat16 g_khi[B_*T_*H_], g_klo[B_*T_*H_];   // pre-scaled by 0.125
__device__ __nv_bfloat16 g_vthi[B_*H_*T_], g_vtlo[B_*H_*T_]; // [b][h][t]
__device__ __nv_bfloat16 g_erhi[T_*H_], g_erlo[T_*H_];
__device__ __nv_bfloat16 g_xhi[B_*T_*C_], g_xlo[B_*T_*C_];   // pre-split x
__device__ __nv_bfloat16 g_wthi[3*H_*C_], g_wtlo[3*H_*C_];   // W transposed [mat][h][c]; Wk pre-scaled

// 36 used 16x16 G segments for the 128-row tile: value = ta*8 + c16
__constant__ unsigned char G_SEGS[36] = {
    24,17,10,3,  32,25,18,11,  40,33,26,19,  48,41,34,27,
    56,49,42,35, 64,57,50,43,  72,65,58,51,  80,73,66,59,
    88,81,74,67
};

// ---------------------------------------------------------------------------
// helpers
// ---------------------------------------------------------------------------
__device__ __forceinline__ void bsplit(float x, __nv_bfloat16& h, __nv_bfloat16& l) {
    h = __float2bfloat16_rn(x);
    l = __float2bfloat16_rn(x - __bfloat162float(h));
}
__device__ __forceinline__ uint32_t smem_u32(const void* p) {
    return (uint32_t)__cvta_generic_to_shared(p);
}
__device__ __forceinline__ void ldsm_x4(uint32_t addr,
    uint32_t& r0, uint32_t& r1, uint32_t& r2, uint32_t& r3)
{
    asm volatile("ldmatrix.sync.aligned.m8n8.x4.shared.b16 {%0,%1,%2,%3}, [%4];"
        : "=r"(r0), "=r"(r1), "=r"(r2), "=r"(r3) : "r"(addr));
}
__device__ __forceinline__ void mmabf(float* c,
    uint32_t a0, uint32_t a1, uint32_t a2, uint32_t a3, uint32_t b0, uint32_t b1)
{
    asm volatile(
        "mma.sync.aligned.m16n8k16.row.col.f32.bf16.bf16.f32 "
        "{%0,%1,%2,%3}, {%4,%5,%6,%7}, {%8,%9}, {%0,%1,%2,%3};"
        : "+f"(c[0]), "+f"(c[1]), "+f"(c[2]), "+f"(c[3])
        : "r"(a0), "r"(a1), "r"(a2), "r"(a3), "r"(b0), "r"(b1));
}

// acc[2][4] += A(16 rows @ar0, 2-plane) x B^T(16 cols @n0*8, 2-plane)
__device__ __forceinline__ void gemm16(
    const uint32_t* __restrict__ Ah, const uint32_t* __restrict__ Al, int ar0,
    const uint32_t* __restrict__ Bh, const uint32_t* __restrict__ Bl, int n0,
    int lane, float (*acc)[4])
{
    const int la = lane & 7, l8 = (lane >> 3) & 1, l16 = lane >> 4;
    uint32_t aAh = smem_u32(Ah + (ar0 + la + l8*8)*SW) + l16*16;
    uint32_t aAl = smem_u32(Al + (ar0 + la + l8*8)*SW) + l16*16;
    uint32_t aBh = smem_u32(Bh + ((n0 + l16)*8 + la)*SW) + l8*16;
    uint32_t aBl = smem_u32(Bl + ((n0 + l16)*8 + la)*SW) + l8*16;
    #pragma unroll
    for (int ck = 0; ck < 4; ++ck) {
        uint32_t a0h,a1h,a2h,a3h, a0l,a1l,a2l,a3l;
        uint32_t p0h,p1h,q0h,q1h, p0l,p1l,q0l,q1l;
        ldsm_x4(aAh + ck*32, a0h,a1h,a2h,a3h);
        ldsm_x4(aAl + ck*32, a0l,a1l,a2l,a3l);
        ldsm_x4(aBh + ck*32, p0h,p1h,q0h,q1h);
        ldsm_x4(aBl + ck*32, p0l,p1l,q0l,q1l);
        mmabf(acc[0], a0h,a1h,a2h,a3h, p0h,p1h);
        mmabf(acc[0], a0l,a1l,a2l,a3l, p0h,p1h);
        mmabf(acc[0], a0h,a1h,a2h,a3h, p0l,p1l);
        mmabf(acc[1], a0h,a1h,a2h,a3h, q0h,q1h);
        mmabf(acc[1], a0l,a1l,a2l,a3l, q0h,q1h);
        mmabf(acc[1], a0h,a1h,a2h,a3h, q0l,q1l);
    }
}

// acc[4][4] += A(16 rows @ar0) x B^T(32 cols @n0*8): A loaded ONCE per ck
__device__ __forceinline__ void gemm16_n4(
    const uint32_t* __restrict__ Ah, const uint32_t* __restrict__ Al, int ar0,
    const uint32_t* __restrict__ Bh, const uint32_t* __restrict__ Bl, int n0,
    int lane, float (*acc)[4])
{
    const int la = lane & 7, l8 = (lane >> 3) & 1, l16 = lane >> 4;
    uint32_t aAh = smem_u32(Ah + (ar0 + la + l8*8)*SW) + l16*16;
    uint32_t aAl = smem_u32(Al + (ar0 + la + l8*8)*SW) + l16*16;
    uint32_t b0h = smem_u32(Bh + ((n0   + l16)*8 + la)*SW) + l8*16;
    uint32_t b1h = smem_u32(Bh + ((n0+2 + l16)*8 + la)*SW) + l8*16;
    uint32_t b0l = smem_u32(Bl + ((n0   + l16)*8 + la)*SW) + l8*16;
    uint32_t b1l = smem_u32(Bl + ((n0+2 + l16)*8 + la)*SW) + l8*16;
    #pragma unroll
    for (int ck = 0; ck < 4; ++ck) {
        uint32_t a0h,a1h,a2h,a3h, a0l,a1l,a2l,a3l;
        uint32_t p0,p1,q0,q1, r0,r1,s0,s1, P0,P1,Q0,Q1, R0,R1,S0,S1;
        ldsm_x4(aAh + ck*32, a0h,a1h,a2h,a3h);
        ldsm_x4(aAl + ck*32, a0l,a1l,a2l,a3l);
        ldsm_x4(b0h + ck*32, p0,p1,q0,q1);
        ldsm_x4(b1h + ck*32, r0,r1,s0,s1);
        ldsm_x4(b0l + ck*32, P0,P1,Q0,Q1);
        ldsm_x4(b1l + ck*32, R0,R1,S0,S1);
        mmabf(acc[0], a0h,a1h,a2h,a3h, p0,p1);
        mmabf(acc[0], a0l,a1l,a2l,a3l, p0,p1);
        mmabf(acc[0], a0h,a1h,a2h,a3h, P0,P1);
        mmabf(acc[1], a0h,a1h,a2h,a3h, q0,q1);
        mmabf(acc[1], a0l,a1l,a2l,a3l, q0,q1);
        mmabf(acc[1], a0h,a1h,a2h,a3h, Q0,Q1);
        mmabf(acc[2], a0h,a1h,a2h,a3h, r0,r1);
        mmabf(acc[2], a0l,a1l,a2l,a3l, r0,r1);
        mmabf(acc[2], a0h,a1h,a2h,a3h, R0,R1);
        mmabf(acc[3], a0h,a1h,a2h,a3h, s0,s1);
        mmabf(acc[3], a0l,a1l,a2l,a3l, s0,s1);
        mmabf(acc[3], a0h,a1h,a2h,a3h, S0,S1);
    }
}

// Proj: acc[8][4] += A(16 rows) x B^T(64 cols)
__device__ __forceinline__ void gemm16_n8(
    const uint32_t* __restrict__ Ah, const uint32_t* __restrict__ Al, int ar0,
    const uint32_t* __restrict__ Bh, const uint32_t* __restrict__ Bl,
    int lane, float (*acc)[4])
{
    const int la = lane & 7, l8 = (lane >> 3) & 1, l16 = lane >> 4;
    uint32_t aAh = smem_u32(Ah + (ar0 + la + l8*8)*SW) + l16*16;
    uint32_t aAl = smem_u32(Al + (ar0 + la + l8*8)*SW) + l16*16;
    uint32_t aBh = smem_u32(Bh + ((l16)*8 + la)*SW) + l8*16;
    uint32_t aBl = smem_u32(Bl + ((l16)*8 + la)*SW) + l8*16;
    #pragma unroll
    for (int ck = 0; ck < 4; ++ck) {
        uint32_t a0h,a1h,a2h,a3h, a0l,a1l,a2l,a3l;
        ldsm_x4(aAh + ck*32, a0h,a1h,a2h,a3h);
        ldsm_x4(aAl + ck*32, a0l,a1l,a2l,a3l);
        #pragma unroll
        for (int p = 0; p < 4; ++p) {
            uint32_t p0h,p1h,q0h,q1h, p0l,p1l,q0l,q1l;
            ldsm_x4(aBh + p*2304 + ck*32, p0h,p1h,q0h,q1h);
            ldsm_x4(aBl + p*2304 + ck*32, p0l,p1l,q0l,q1l);
            mmabf(acc[2*p  ], a0h,a1h,a2h,a3h, p0h,p1h);
            mmabf(acc[2*p  ], a0l,a1l,a2l,a3l, p0h,p1h);
            mmabf(acc[2*p  ], a0h,a1h,a2h,a3h, p0l,p1l);
            mmabf(acc[2*p+1], a0h,a1h,a2h,a3h, q0h,q1h);
            mmabf(acc[2*p+1], a0l,a1l,a2l,a3l, q0h,q1h);
            mmabf(acc[2*p+1], a0h,a1h,a2h,a3h, q0l,q1l);
        }
    }
}

// ---------------------------------------------------------------------------
// Prep kernels: split Er, x, W into bf16 hi/lo planes (once).
// W is transposed to [mat][h][c]; Wk pre-scaled by 0.125 (exact pow-2).
// ---------------------------------------------------------------------------
__global__ void er_prep(const float* __restrict__ Er)
{
    int i = blockIdx.x * blockDim.x + threadIdx.x;
    if (i < T_*H_) {
        __nv_bfloat16 h, l;
        bsplit(Er[i], h, l);
        g_erhi[i] = h; g_erlo[i] = l;
    }
}

__global__ void x_prep(const float* __restrict__ x)
{
    int i4 = (blockIdx.x * blockDim.x + threadIdx.x) * 4;
    if (i4 < B_*T_*C_) {
        float4 v = *(const float4*)&x[i4];
        __nv_bfloat16 h0,l0,h1,l1;
        bsplit(v.x, h0, l0); bsplit(v.y, h1, l1);
        __nv_bfloat162 th; th.x = h0; th.y = h1;
        __nv_bfloat162 tl; tl.x = l0; tl.y = l1;
        *(__nv_bfloat162*)&g_xhi[i4]     = th;
        *(__nv_bfloat162*)&g_xlo[i4]     = tl;
        bsplit(v.z, h0, l0); bsplit(v.w, h1, l1);
        th.x = h0; th.y = h1; tl.x = l0; tl.y = l1;
        *(__nv_bfloat162*)&g_xhi[i4 + 2] = th;
        *(__nv_bfloat162*)&g_xlo[i4 + 2] = tl;
    }
}

__global__ void w_prep(const float* __restrict__ Wq,
                       const float* __restrict__ Wk,
                       const float* __restrict__ Wv)
{
    int i = blockIdx.x * blockDim.x + threadIdx.x;   // 3*512*64
    if (i < 3*C_*H_) {
        int mat = i / (C_*H_);
        int rem = i - mat*(C_*H_);
        int c = rem >> 6, h = rem & 63;
        const float* W = (mat == 0) ? Wq : (mat == 1) ? Wk : Wv;
        float v = W[(size_t)c*H_ + h];
        if (mat == 1) v *= 0.125f;       // fold attention scale into Wk
        __nv_bfloat16 hb, lb;
        bsplit(v, hb, lb);
        size_t o = (size_t)(mat*H_ + h)*C_ + c;
        g_wthi[o] = hb; g_wtlo[o] = lb;
    }
}

// ---------------------------------------------------------------------------
// Kernel 1: QKV projection — per-matrix (proven shell), fills are now pure
// uint4 copies from the pre-split planes. V written transposed.
// ---------------------------------------------------------------------------
#define PXH 0
#define PXL 4608
#define PWH 9216
#define PWL 11520
#define PSMEM_FLOATS 13824
#define PSMEM_BYTES (PSMEM_FLOATS*4)

__global__ __launch_bounds__(256) void proj_kernel()
{
    extern __shared__ float sm[];
    uint32_t* sXH = (uint32_t*)(sm + PXH);
    uint32_t* sXL = (uint32_t*)(sm + PXL);
    uint32_t* sWH = (uint32_t*)(sm + PWH);
    uint32_t* sWL = (uint32_t*)(sm + PWL);

    const int tid  = threadIdx.x;
    const int w    = tid >> 5;
    const int lane = tid & 31;
    const int gid  = lane >> 2;
    const int tig  = lane & 3;
    const int row0 = blockIdx.x * 128;
    const int mat  = blockIdx.y;

    float acc[8][4];
    #pragma unroll
    for (int n = 0; n < 8; ++n)
        #pragma unroll
        for (int j = 0; j < 4; ++j) acc[n][j] = 0.f;

    for (int kc = 0; kc < C_; kc += 64) {
        __syncthreads();
        {   // x tile copy: 128 rows x 64 bf16, both planes
            int rr = tid >> 1, c0 = (tid & 1) * 32;
            const uint4* xh = (const uint4*)&g_xhi[(size_t)(row0 + rr)*C_ + kc + c0];
            const uint4* xl = (const uint4*)&g_xlo[(size_t)(row0 + rr)*C_ + kc + c0];
            uint4* dh = (uint4*)&sXH[rr*SW + c0/2];
            uint4* dl = (uint4*)&sXL[rr*SW + c0/2];
            #pragma unroll
            for (int u = 0; u < 4; ++u) { dh[u] = xh[u]; dl[u] = xl[u]; }
        }
        {   // W tile copy: 64 rows (h) x 64 bf16 (c), both planes
            int h = tid >> 2, c0 = (tid & 3) * 16;
            const uint4* wh = (const uint4*)&g_wthi[(size_t)(mat*H_ + h)*C_ + kc + c0];
            const uint4* wl = (const uint4*)&g_wtlo[(size_t)(mat*H_ + h)*C_ + kc + c0];
            uint4* dh = (uint4*)&sWH[h*SW + c0/2];
            uint4* dl = (uint4*)&sWL[h*SW + c0/2];
            dh[0] = wh[0]; dh[1] = wh[1];
            dl[0] = wl[0]; dl[1] = wl[1];
        }
        __syncthreads();
        gemm16_n8(sXH, sXL, w*16, sWH, sWL, lane, acc);
    }

    const int r = row0 + w*16 + gid;
    if (mat < 2) {
        __nv_bfloat16* ghi = (mat == 0) ? g_qhi : g_khi;
        __nv_bfloat16* glo = (mat == 0) ? g_qlo : g_klo;
        #pragma unroll
        for (int n = 0; n < 8; ++n) {
            int h0 = n*8 + 2*tig;
            __nv_bfloat16 h0b,l0b,h1b,l1b;
            bsplit(acc[n][0], h0b, l0b); bsplit(acc[n][1], h1b, l1b);
            __nv_bfloat162 th; th.x = h0b; th.y = h1b;
            __nv_bfloat162 tl; tl.x = l0b; tl.y = l1b;
            *(__nv_bfloat162*)&ghi[(size_t)r*H_ + h0] = th;
            *(__nv_bfloat162*)&glo[(size_t)r*H_ + h0] = tl;
            bsplit(acc[n][2], h0b, l0b); bsplit(acc[n][3], h1b, l1b);
            th.x = h0b; th.y = h1b; tl.x = l0b; tl.y = l1b;
            *(__nv_bfloat162*)&ghi[(size_t)(r+8)*H_ + h0] = th;
            *(__nv_bfloat162*)&glo[(size_t)(r+8)*H_ + h0] = tl;
        }
    } else {
        #pragma unroll
        for (int n = 0; n < 8; ++n) {
            int h0 = n*8 + 2*tig;
            #pragma unroll
            for (int rr = 0; rr < 2; ++rr) {
                int rg = r + rr*8;
                int b  = rg >> 11, t = rg & 2047;
                __nv_bfloat16 hb, lb;
                bsplit(acc[n][rr*2], hb, lb);
                g_vthi[((size_t)b*H_ + h0    )*T_ + t] = hb;
                g_vtlo[((size_t)b*H_ + h0    )*T_ + t] = lb;
                bsplit(acc[n][rr*2+1], hb, lb);
                g_vthi[((size_t)b*H_ + h0 + 1)*T_ + t] = hb;
                g_vtlo[((size_t)b*H_ + h0 + 1)*T_ + t] = lb;
            }
        }
    }
}

// ---------------------------------------------------------------------------
// Kernel 2: attention (R14, unchanged): 128-row tiles + E ring buffer.
// ---------------------------------------------------------------------------
#define AQH   0        /* 128 x SW */
#define AQL   4608
#define AKH   9216     /* 64 x SW; P hi aliases [9216,13824) */
#define AKL   11520
#define AQCH  13824    /* P lo aliases [13824,18432) */
#define AQCL  16128
#define AVH   18432
#define AVL   20736
#define AEH   23040    /* 192 x SW ring */
#define AEL   29952
#define AGD   36864    /* 128 x 68 fp32 diagonal G */
#define ADIAG 45568
#define ASUM  45696    /* 2 x 128 */
#define ASMEM_FLOATS 45952
#define ASMEM_BYTES (ASMEM_FLOATS*4)

__global__ __launch_bounds__(512) void attn_kernel(
    const float* __restrict__ Er,
    float* __restrict__ out)
{
    extern __shared__ float sm[];
    uint32_t* sQH  = (uint32_t*)(sm + AQH);
    uint32_t* sQL  = (uint32_t*)(sm + AQL);
    uint32_t* sKH  = (uint32_t*)(sm + AKH);
    uint32_t* sKL  = (uint32_t*)(sm + AKL);
    uint32_t* sQCH = (uint32_t*)(sm + AQCH);
    uint32_t* sQCL = (uint32_t*)(sm + AQCL);
    uint32_t* sVH  = (uint32_t*)(sm + AVH);
    uint32_t* sVL  = (uint32_t*)(sm + AVL);
    uint32_t* sEH  = (uint32_t*)(sm + AEH);
    uint32_t* sEL  = (uint32_t*)(sm + AEL);
    uint32_t* sPH  = (uint32_t*)(sm + AKH);    // alias over K+Qc (dead by bar 3)
    uint32_t* sPL  = (uint32_t*)(sm + AQCH);
    float*    sGd  = sm + AGD;
    float*    sDiag= sm + ADIAG;
    float*    sSum = sm + ASUM;

    const int tid  = threadIdx.x;
    const int w    = tid >> 5;
    const int lane = tid & 31;
    const int gid  = lane >> 2;
    const int tig  = lane & 3;
    const int wr   = w & 7;
    const int wg   = w >> 3;
    const int b    = blockIdx.x;               // batch
    const int mm   = 15 - (int)blockIdx.y;     // big tiles launch first
    const int t0   = mm * 128;
    const size_t bT = (size_t)b * T_;
    const int r0   = wr*16 + gid;

    const int frr = tid >> 3;           // 64-row fill index
    const int fh8 = tid & 7;            // 8 x 16B segments

    uint4 z = make_uint4(0u,0u,0u,0u);

    {   // prologue: Q planes (128 rows) + E ring blocks 1,2
        #pragma unroll
        for (int k = 0; k < 2; ++k) {
            int lin = tid + k*512;
            int rr = lin >> 3, sg = lin & 7;
            *(uint4*)&sQH[rr*SW + sg*4] =
                *(const uint4*)&g_qhi[(bT + t0 + rr)*H_ + sg*8];
            *(uint4*)&sQL[rr*SW + sg*4] =
                *(const uint4*)&g_qlo[(bT + t0 + rr)*H_ + sg*8];
            int e = t0 - 1 + rr;               // a = 64 + rr
            uint4 vh = z, vl = z;
            if (e >= 0) {
                vh = *(const uint4*)&g_erhi[(size_t)e*H_ + sg*8];
                vl = *(const uint4*)&g_erlo[(size_t)e*H_ + sg*8];
            }
            *(uint4*)&sEH[(64 + rr)*SW + sg*4] = vh;
            *(uint4*)&sEL[(64 + rr)*SW + sg*4] = vl;
        }
    }
    __syncthreads();

    {   // diag[r] = q[t0+r] . Er[T-1], 128 rows (4 threads/row)
        int r = tid >> 2, qd = tid & 3;
        const float* er = Er + (size_t)(T_-1) * H_;
        const __nv_bfloat16* qh = (const __nv_bfloat16*)sQH;
        const __nv_bfloat16* ql = (const __nv_bfloat16*)sQL;
        float p = 0.f;
        #pragma unroll
        for (int hh = 0; hh < 16; ++hh) {
            int h = qd*16 + hh;
            float qv = __bfloat162float(qh[r*(2*SW) + h]) +
                       __bfloat162float(ql[r*(2*SW) + h]);
            p += qv * er[h];
        }
        p += __shfl_xor_sync(0xffffffffu, p, 1);
        p += __shfl_xor_sync(0xffffffffu, p, 2);
        if (qd == 0) sDiag[r] = p;
    }

    float o[4][4];
    float lr0 = 0.f, lr1 = 0.f;
    #pragma unroll
    for (int n = 0; n < 4; ++n)
        #pragma unroll
        for (int j = 0; j < 4; ++j) o[n][j] = 0.f;

    const int n_iter = 2*mm + 2;
    int pb0 = 0;                           // (-jt) mod 3
    for (int jt = 0; jt < n_iter; ++jt) {
        const int s0 = jt * 64;
        const int d  = t0 - s0;            // >= -64

        // prefetch K/V/Qc + new E block gmem -> regs (overlaps barrier wait)
        uint4 pkh = *(const uint4*)&g_khi[(bT + s0 + frr)*H_ + fh8*8];
        uint4 pkl = *(const uint4*)&g_klo[(bT + s0 + frr)*H_ + fh8*8];
        uint4 pvh = *(const uint4*)&g_vthi[((size_t)b*H_ + frr)*T_ + s0 + fh8*8];
        uint4 pvl = *(const uint4*)&g_vtlo[((size_t)b*H_ + frr)*T_ + s0 + fh8*8];
        int qr = s0 + 1 + frr;
        uint4 pqh = z, pql = z;
        if (qr < T_) {
            pqh = *(const uint4*)&g_qhi[(bT + qr)*H_ + fh8*8];
            pql = *(const uint4*)&g_qlo[(bT + qr)*H_ + fh8*8];
        }
        int e = d - 65 + frr;              // logical block 0 row
        uint4 peh = z, pel = z;
        if (e >= 0) {
            peh = *(const uint4*)&g_erhi[(size_t)e*H_ + fh8*8];
            pel = *(const uint4*)&g_erlo[(size_t)e*H_ + fh8*8];
        }

        __syncthreads();   // (1) prev PV done; tiles free

        *(uint4*)&sKH[frr*SW + fh8*4] = pkh;
        *(uint4*)&sKL[frr*SW + fh8*4] = pkl;
        *(uint4*)&sQCH[frr*SW + fh8*4] = pqh;
        *(uint4*)&sQCL[frr*SW + fh8*4] = pql;
        *(uint4*)&sVH[frr*SW + fh8*4] = pvh;
        *(uint4*)&sVL[frr*SW + fh8*4] = pvl;
        *(uint4*)&sEH[(pb0*64 + frr)*SW + fh8*4] = peh;
        *(uint4*)&sEL[(pb0*64 + frr)*SW + fh8*4] = pel;
        __syncthreads();   // (2) tiles ready

        // G: 36 16x16 segments (ring-remapped A rows), diagonal scatter
        for (int si = w; si < 36; si += 16) {
            int seg = G_SEGS[si];
            int ta = seg >> 3, c16 = seg & 7;
            int pb = pb0 + (ta >> 2); if (pb >= 3) pb -= 3;
            int abase = pb*64 + (ta & 3)*16;
            float g[2][4];
            #pragma unroll
            for (int n = 0; n < 2; ++n)
                #pragma unroll
                for (int j = 0; j < 4; ++j) g[n][j] = 0.f;
            gemm16(sEH, sEL, abase, sQCH, sQCL, c16*2, lane, g);
            int ar = ta*16 + gid;
            #pragma unroll
            for (int n = 0; n < 2; ++n) {
                int cb = (c16*2+n)*8 + 2*tig;
                int rr;
                rr = ar + cb - 63;
                if ((unsigned)rr < 128u) sGd[rr*68 + cb]     = g[n][0];
                rr = ar + cb - 62;
                if ((unsigned)rr < 128u) sGd[rr*68 + cb + 1] = g[n][1];
                rr = ar + cb - 55;
                if ((unsigned)rr < 128u) sGd[rr*68 + cb]     = g[n][2];
                rr = ar + cb - 54;
                if ((unsigned)rr < 128u) sGd[rr*68 + cb + 1] = g[n][3];
            }
        }

        // S = Q x K^T (16 rows x 32 cols per warp)
        float s[4][4];
        #pragma unroll
        for (int n = 0; n < 4; ++n)
            #pragma unroll
            for (int j = 0; j < 4; ++j) s[n][j] = 0.f;
        gemm16_n4(sQH, sQL, wr*16, sKH, sKL, wg*4, lane, s);
        __syncthreads();   // (3) sGd complete; K/Qc dead -> P region free

        // assemble + exp + P store
        const bool dt = (d < 64);
        const int cd0 = r0 + d, cd1 = r0 + 8 + d;
        __nv_bfloat16* pH = (__nv_bfloat16*)sPH;
        __nv_bfloat16* pL = (__nv_bfloat16*)sPL;
        #pragma unroll
        for (int n = 0; n < 4; ++n) {
            int c0 = (wg*4+n)*8 + 2*tig;
            float2 gd0 = *(const float2*)&sGd[ r0   *68 + c0];
            float2 gd1 = *(const float2*)&sGd[(r0+8)*68 + c0];
            float v0 = s[n][0] + gd0.x;
            float v1 = s[n][1] + gd0.y;
            float v2 = s[n][2] + gd1.x;
            float v3 = s[n][3] + gd1.y;
            if (dt) {
                if (c0     > cd0) v0 = -3.0e38f; else if (c0     == cd0) v0 += sDiag[r0];
                if (c0 + 1 > cd0) v1 = -3.0e38f; else if (c0 + 1 == cd0) v1 += sDiag[r0];
                if (c0     > cd1) v2 = -3.0e38f; else if (c0     == cd1) v2 += sDiag[r0+8];
                if (c0 + 1 > cd1) v3 = -3.0e38f; else if (c0 + 1 == cd1) v3 += sDiag[r0+8];
            }
            float p0 = __expf(v0), p1 = __expf(v1);
            float p2 = __expf(v2), p3 = __expf(v3);
            lr0 += p0 + p1;
            lr1 += p2 + p3;
            __nv_bfloat16 h0b,l0b,h1b,l1b;
            bsplit(p0, h0b, l0b); bsplit(p1, h1b, l1b);
            __nv_bfloat162 th; th.x = h0b; th.y = h1b;
            __nv_bfloat162 tl; tl.x = l0b; tl.y = l1b;
            *(__nv_bfloat162*)&pH[r0*(2*SW) + c0] = th;
            *(__nv_bfloat162*)&pL[r0*(2*SW) + c0] = tl;
            bsplit(p2, h0b, l0b); bsplit(p3, h1b, l1b);
            th.x = h0b; th.y = h1b; tl.x = l0b; tl.y = l1b;
            *(__nv_bfloat162*)&pH[(r0+8)*(2*SW) + c0] = th;
            *(__nv_bfloat162*)&pL[(r0+8)*(2*SW) + c0] = tl;
        }
        __syncthreads();   // (4) sP complete

        // O += P x V^T (16 rows x 32 h-cols per warp)
        gemm16_n4(sPH, sPL, wr*16, sVH, sVL, wg*4, lane, o);

        pb0 -= 1; if (pb0 < 0) pb0 = 2;    // pb0 = (-jt) mod 3
    }

    // final denominator reduce
    lr0 += __shfl_xor_sync(0xffffffffu, lr0, 1);
    lr0 += __shfl_xor_sync(0xffffffffu, lr0, 2);
    lr1 += __shfl_xor_sync(0xffffffffu, lr1, 1);
    lr1 += __shfl_xor_sync(0xffffffffu, lr1, 2);
    if (tig == 0) {
        sSum[wg*128 + r0]     = lr0;
        sSum[wg*128 + r0 + 8] = lr1;
    }
    __syncthreads();
    float tl0 = sSum[r0]     + sSum[128 + r0];
    float tl1 = sSum[r0 + 8] + sSum[128 + r0 + 8];
    float inv0 = 1.f / tl0;
    float inv1 = 1.f / tl1;
    #pragma unroll
    for (int n = 0; n < 4; ++n) {
        int c0 = (wg*4+n)*8 + 2*tig;
        *(float2*)&out[(bT + t0 + r0    )*H_ + c0] =
            make_float2(o[n][0]*inv0, o[n][1]*inv0);
        *(float2*)&out[(bT + t0 + r0 + 8)*H_ + c0] =
            make_float2(o[n][2]*inv1, o[n][3]*inv1);
    }
}

// ---------------------------------------------------------------------------
extern "C" void kernel_launch(void* const* d_in, const int* in_sizes, int n_in,
                              void* d_out, int out_size)
{
    const float* x  = (const float*)d_in[0];
    const float* Wq = (const float*)d_in[1];
    const float* Wk = (const float*)d_in[2];
    const float* Wv = (const float*)d_in[3];
    const float* Er = (const float*)d_in[4];
    float* out = (float*)d_out;

    cudaFuncSetAttribute(proj_kernel,
                         cudaFuncAttributeMaxDynamicSharedMemorySize, PSMEM_BYTES);
    cudaFuncSetAttribute(attn_kernel,
                         cudaFuncAttributeMaxDynamicSharedMemorySize, ASMEM_BYTES);

    er_prep<<<(T_*H_ + 255)/256, 256>>>(Er);
    x_prep<<<(B_*T_*C_/4 + 255)/256, 256>>>(x);
    w_prep<<<(3*C_*H_ + 255)/256, 256>>>(Wq, Wk, Wv);
    proj_kernel<<<dim3(256, 3), 256, PSMEM_BYTES>>>();
    attn_kernel<<<dim3(16, 16), 512, ASMEM_BYTES>>>(Er, out);
}